// round 5
// baseline (speedup 1.0000x reference)
#include <cuda_runtime.h>
#include <cstdint>

// ---------------------------------------------------------------------------
// Attention_layer: N=B*H*W=32768 tiny attention problems, fused, fp32 with
// packed f32x2 FMA. One warp per position, one CTA per (b, h, 8-wide w tile).
// R4: software-pipelined phases (explicit prefetch double-buffering) to hide
// LDS latency at 2 warps/SMSP; phase A split into (k,q) and (v) passes for
// register headroom.
// ---------------------------------------------------------------------------

#define ULL unsigned long long

__device__ __forceinline__ ULL d2(float x) {
    ULL r; asm("mov.b64 %0,{%1,%1};" : "=l"(r) : "f"(x)); return r;
}
__device__ __forceinline__ void fma2(ULL& a, ULL b, ULL c) {
    asm("fma.rn.f32x2 %0,%1,%2,%0;" : "+l"(a) : "l"(b), "l"(c));
}
__device__ __forceinline__ void add2(ULL& a, ULL b) {
    asm("add.rn.f32x2 %0,%1,%0;" : "+l"(a) : "l"(b));
}
__device__ __forceinline__ float2 unpk(ULL a) {
    float lo, hi; asm("mov.b64 {%0,%1},%2;" : "=f"(lo), "=f"(hi) : "l"(a));
    return make_float2(lo, hi);
}
__device__ __forceinline__ float ex2(float x) {
    float r; asm("ex2.approx.f32 %0,%1;" : "=f"(r) : "f"(x)); return r;
}

// Problem constants
static constexpr int B  = 8;
static constexpr int CH = 64;
static constexpr int D  = 32;
static constexpr int H  = 64;
static constexpr int W  = 64;
static constexpr int S  = 32;
static constexpr int WT = 8;            // w-tile per CTA (= warps per CTA)
static constexpr int HW = H * W;

// smem layout (floats)
static constexpr int XSTRIDE  = CH * D + 4;           // 2052
static constexpr int OFF_X    = 0;
static constexpr int OFF_WKT  = OFF_X + WT * XSTRIDE; // 16416
static constexpr int OFF_WQT  = OFF_WKT + CH * S;
static constexpr int OFF_WVT  = OFF_WQT + CH * S;
static constexpr int OFF_WOT  = OFF_WVT + CH * S;     // [s][c]
static constexpr int OFF_BK   = OFF_WOT + S * CH;
static constexpr int OFF_BQ   = OFF_BK + S;
static constexpr int OFF_BV   = OFF_BQ + S;
static constexpr int OFF_BO   = OFF_BV + S;
static constexpr int OFF_SCR  = OFF_BO + CH;
static constexpr int RP       = 36;
static constexpr int SCR_PW   = 3 * 32 * RP;
static constexpr int OFF_OUT  = OFF_SCR + WT * SCR_PW;
static constexpr int SMEM_FLOATS = OFF_OUT + CH * WT;
static constexpr size_t SMEM_BYTES = (size_t)SMEM_FLOATS * 4;

__global__ __launch_bounds__(256, 1)
void attn_fused_kernel(const float* __restrict__ x,
                       const float* __restrict__ Wk, const float* __restrict__ bk,
                       const float* __restrict__ Wq, const float* __restrict__ bq,
                       const float* __restrict__ Wv, const float* __restrict__ bv,
                       const float* __restrict__ Wo, const float* __restrict__ bo,
                       const float* __restrict__ factor,
                       float* __restrict__ out)
{
    extern __shared__ float sm[];
    const int tid  = threadIdx.x;
    const int blk  = blockIdx.x;
    const int b    = blk >> 9;
    const int rem  = blk & 511;
    const int h    = rem >> 3;
    const int w0   = (rem & 7) << 3;

    // ---- Stage x tile FIRST (long-latency DRAM loads issue early) ----
    // [c][d][w0..w0+7] gmem -> smem [w][c*32+d]
    const float* base_in = x + (size_t)b * (CH * D) * HW + h * W + w0;
    #pragma unroll 4
    for (int it = 0; it < 32; ++it) {
        int idx = it * 256 + tid;
        int cd  = idx >> 2;
        int w2  = (idx & 3) << 1;
        float2 v = *(const float2*)(base_in + (size_t)cd * HW + w2);
        sm[OFF_X + w2 * XSTRIDE + cd]       = v.x;
        sm[OFF_X + (w2 + 1) * XSTRIDE + cd] = v.y;
    }

    // ---- Stage weights (transposed) ----
    for (int i = tid; i < CH * S; i += 256) {
        int c = i >> 5, s = i & 31;
        sm[OFF_WKT + i] = Wk[s * CH + c];
        sm[OFF_WQT + i] = Wq[s * CH + c];
        sm[OFF_WVT + i] = Wv[s * CH + c];
        int s2 = i >> 6, c2 = i & 63;
        sm[OFF_WOT + i] = Wo[c2 * S + s2];
    }
    if (tid < S) {
        sm[OFF_BK + tid] = bk[tid];
        sm[OFF_BQ + tid] = bq[tid];
        sm[OFF_BV + tid] = bv[tid];
    }
    if (tid < CH) sm[OFF_BO + tid] = bo[tid];
    __syncthreads();

    const int warp = tid >> 5;
    const int lane = tid & 31;
    const int sg   = lane >> 3;  // 0..3
    const int jg   = lane & 7;   // 0..7

    float* xw   = sm + OFF_X + warp * XSTRIDE;
    float* bufA = sm + OFF_SCR + warp * SCR_PW;   // kT, later a
    float* bufQ = bufA + 32 * RP;                 // qT, later om
    float* bufV = bufQ + 32 * RP;                 // vT

    const float* xbase  = xw + jg * 4;
    const float* wkbase = sm + OFF_WKT + sg * 8;
    const float* wqbase = sm + OFF_WQT + sg * 8;
    const float* wvbase = sm + OFF_WVT + sg * 8;

    // ================= Phase A pass 1: k and q projections =================
    ULL ak[4][4], aq[4][4];
    {
        const ULL* bk2 = (const ULL*)(sm + OFF_BK);
        const ULL* bq2 = (const ULL*)(sm + OFF_BQ);
        #pragma unroll
        for (int sp = 0; sp < 4; ++sp) {
            ULL bK = bk2[sg * 4 + sp], bQ = bq2[sg * 4 + sp];
            #pragma unroll
            for (int td = 0; td < 4; ++td) { ak[sp][td] = bK; aq[sp][td] = bQ; }
        }
    }
    {
        // software pipeline: prefetch c+1 while FMA'ing c
        float4 xv = *(const float4*)(xbase);
        ulonglong2 wka = ((const ulonglong2*)wkbase)[0];
        ulonglong2 wkb = ((const ulonglong2*)wkbase)[1];
        ulonglong2 wqa = ((const ulonglong2*)wqbase)[0];
        ulonglong2 wqb = ((const ulonglong2*)wqbase)[1];
        #pragma unroll 4
        for (int c = 0; c < CH; ++c) {
            const int cn = (c + 1) & 63;
            float4 xv_n = *(const float4*)(xbase + cn * 32);
            ulonglong2 wka_n = ((const ulonglong2*)(wkbase + cn * 32))[0];
            ulonglong2 wkb_n = ((const ulonglong2*)(wkbase + cn * 32))[1];
            ulonglong2 wqa_n = ((const ulonglong2*)(wqbase + cn * 32))[0];
            ulonglong2 wqb_n = ((const ulonglong2*)(wqbase + cn * 32))[1];

            ULL xd[4] = {d2(xv.x), d2(xv.y), d2(xv.z), d2(xv.w)};
            #pragma unroll
            for (int td = 0; td < 4; ++td) {
                fma2(ak[0][td], wka.x, xd[td]); fma2(ak[1][td], wka.y, xd[td]);
                fma2(ak[2][td], wkb.x, xd[td]); fma2(ak[3][td], wkb.y, xd[td]);
                fma2(aq[0][td], wqa.x, xd[td]); fma2(aq[1][td], wqa.y, xd[td]);
                fma2(aq[2][td], wqb.x, xd[td]); fma2(aq[3][td], wqb.y, xd[td]);
            }
            xv = xv_n; wka = wka_n; wkb = wkb_n; wqa = wqa_n; wqb = wqb_n;
        }
    }
    // Store transposed: kT/qT [d][s]
    #pragma unroll
    for (int td = 0; td < 4; ++td) {
        int d = jg * 4 + td;
        ULL* kT = (ULL*)(bufA + d * RP + sg * 8);
        ULL* qT = (ULL*)(bufQ + d * RP + sg * 8);
        #pragma unroll
        for (int sp = 0; sp < 4; ++sp) { kT[sp] = ak[sp][td]; qT[sp] = aq[sp][td]; }
    }

    // ================= Phase A pass 2: v projection ========================
    ULL av[4][4];
    {
        const ULL* bv2 = (const ULL*)(sm + OFF_BV);
        #pragma unroll
        for (int sp = 0; sp < 4; ++sp) {
            ULL bV = bv2[sg * 4 + sp];
            #pragma unroll
            for (int td = 0; td < 4; ++td) av[sp][td] = bV;
        }
        float4 xv = *(const float4*)(xbase);
        ulonglong2 wva = ((const ulonglong2*)wvbase)[0];
        ulonglong2 wvb = ((const ulonglong2*)wvbase)[1];
        #pragma unroll 4
        for (int c = 0; c < CH; ++c) {
            const int cn = (c + 1) & 63;
            float4 xv_n = *(const float4*)(xbase + cn * 32);
            ulonglong2 wva_n = ((const ulonglong2*)(wvbase + cn * 32))[0];
            ulonglong2 wvb_n = ((const ulonglong2*)(wvbase + cn * 32))[1];

            ULL xd[4] = {d2(xv.x), d2(xv.y), d2(xv.z), d2(xv.w)};
            #pragma unroll
            for (int td = 0; td < 4; ++td) {
                fma2(av[0][td], wva.x, xd[td]); fma2(av[1][td], wva.y, xd[td]);
                fma2(av[2][td], wvb.x, xd[td]); fma2(av[3][td], wvb.y, xd[td]);
            }
            xv = xv_n; wva = wva_n; wvb = wvb_n;
        }
    }
    #pragma unroll
    for (int td = 0; td < 4; ++td) {
        int d = jg * 4 + td;
        ULL* vT = (ULL*)(bufV + d * RP + sg * 8);
        #pragma unroll
        for (int sp = 0; sp < 4; ++sp) vT[sp] = av[sp][td];
    }
    __syncwarp();

    // ================= Phase B: scores[i][j] = sum_s k[s][i] q[s][j] =======
    ULL acc[8][4];
    #pragma unroll
    for (int ti = 0; ti < 8; ++ti)
        #pragma unroll
        for (int tj = 0; tj < 4; ++tj) acc[ti][tj] = 0ull;

    {
        ulonglong2 kk[8], qq[4];
        #pragma unroll
        for (int ti = 0; ti < 8; ++ti)
            kk[ti] = *(const ulonglong2*)(bufA + (4 * ti + sg) * RP);
        #pragma unroll
        for (int tj = 0; tj < 4; ++tj)
            qq[tj] = *(const ulonglong2*)(bufQ + (8 * tj + jg) * RP);

        #pragma unroll 2
        for (int sq = 0; sq < 8; ++sq) {
            const int sn = (sq + 1) & 7;
            ulonglong2 kkn[8], qqn[4];
            #pragma unroll
            for (int ti = 0; ti < 8; ++ti)
                kkn[ti] = *(const ulonglong2*)(bufA + (4 * ti + sg) * RP + sn * 4);
            #pragma unroll
            for (int tj = 0; tj < 4; ++tj)
                qqn[tj] = *(const ulonglong2*)(bufQ + (8 * tj + jg) * RP + sn * 4);

            #pragma unroll
            for (int ti = 0; ti < 8; ++ti)
                #pragma unroll
                for (int tj = 0; tj < 4; ++tj) {
                    fma2(acc[ti][tj], kk[ti].x, qq[tj].x);
                    fma2(acc[ti][tj], kk[ti].y, qq[tj].y);
                }
            #pragma unroll
            for (int ti = 0; ti < 8; ++ti) kk[ti] = kkn[ti];
            #pragma unroll
            for (int tj = 0; tj < 4; ++tj) qq[tj] = qqn[tj];
        }
    }
    float sc[8][4];
    #pragma unroll
    for (int ti = 0; ti < 8; ++ti)
        #pragma unroll
        for (int tj = 0; tj < 4; ++tj) { float2 u = unpk(acc[ti][tj]); sc[ti][tj] = u.x + u.y; }

    // ================= Phase C: softmax over i (per column j) ==============
    const float CEXP = 0.17677669529663687f * 1.44269504088896340f;
    #pragma unroll
    for (int tj = 0; tj < 4; ++tj) {
        float m = sc[0][tj];
        #pragma unroll
        for (int ti = 1; ti < 8; ++ti) m = fmaxf(m, sc[ti][tj]);
        m = fmaxf(m, __shfl_xor_sync(0xffffffffu, m, 8));
        m = fmaxf(m, __shfl_xor_sync(0xffffffffu, m, 16));
        float sum = 0.f;
        #pragma unroll
        for (int ti = 0; ti < 8; ++ti) {
            float e = ex2((sc[ti][tj] - m) * CEXP);
            sc[ti][tj] = e; sum += e;
        }
        sum += __shfl_xor_sync(0xffffffffu, sum, 8);
        sum += __shfl_xor_sync(0xffffffffu, sum, 16);
        float r = 1.0f / sum;
        #pragma unroll
        for (int ti = 0; ti < 8; ++ti) sc[ti][tj] *= r;
    }
    // store a[i][j] into bufA (k dead)
    #pragma unroll
    for (int ti = 0; ti < 8; ++ti) {
        int i = 4 * ti + sg;
        #pragma unroll
        for (int tj = 0; tj < 4; ++tj) bufA[i * RP + 8 * tj + jg] = sc[ti][tj];
    }
    __syncwarp();

    // ================= Phase D: o[s][j] = sum_d v[s][d] a[d][j] ============
    ULL ao[4][4];
    #pragma unroll
    for (int sp = 0; sp < 4; ++sp)
        #pragma unroll
        for (int tj = 0; tj < 4; ++tj) ao[sp][tj] = 0ull;

    {
        const ulonglong2* vp0 = (const ulonglong2*)(bufV + sg * 8);
        ulonglong2 va = vp0[0], vb = vp0[1];
        float a0 = bufA[jg], a1 = bufA[8 + jg], a2 = bufA[16 + jg], a3 = bufA[24 + jg];
        #pragma unroll 4
        for (int d = 0; d < D; ++d) {
            const int dn = (d + 1) & 31;
            const ulonglong2* vpn = (const ulonglong2*)(bufV + dn * RP + sg * 8);
            ulonglong2 va_n = vpn[0], vb_n = vpn[1];
            float a0n = bufA[dn * RP + jg];
            float a1n = bufA[dn * RP + 8 + jg];
            float a2n = bufA[dn * RP + 16 + jg];
            float a3n = bufA[dn * RP + 24 + jg];

            ULL ad[4] = {d2(a0), d2(a1), d2(a2), d2(a3)};
            #pragma unroll
            for (int tj = 0; tj < 4; ++tj) {
                fma2(ao[0][tj], va.x, ad[tj]); fma2(ao[1][tj], va.y, ad[tj]);
                fma2(ao[2][tj], vb.x, ad[tj]); fma2(ao[3][tj], vb.y, ad[tj]);
            }
            va = va_n; vb = vb_n; a0 = a0n; a1 = a1n; a2 = a2n; a3 = a3n;
        }
    }

    // ================= Phase E: om[s] = mean_j o[s][j] =====================
    #pragma unroll
    for (int sp = 0; sp < 4; ++sp) {
        ULL s2 = ao[sp][0];
        add2(s2, ao[sp][1]); add2(s2, ao[sp][2]); add2(s2, ao[sp][3]);
        float2 u = unpk(s2);
        float o0 = u.x, o1 = u.y;
        o0 += __shfl_xor_sync(0xffffffffu, o0, 1);
        o0 += __shfl_xor_sync(0xffffffffu, o0, 2);
        o0 += __shfl_xor_sync(0xffffffffu, o0, 4);
        o1 += __shfl_xor_sync(0xffffffffu, o1, 1);
        o1 += __shfl_xor_sync(0xffffffffu, o1, 2);
        o1 += __shfl_xor_sync(0xffffffffu, o1, 4);
        if (jg == 0) {
            bufQ[sg * 8 + 2 * sp]     = o0 * (1.0f / 32.0f);
            bufQ[sg * 8 + 2 * sp + 1] = o1 * (1.0f / 32.0f);
        }
    }
    __syncwarp();

    // ================= Phase F: mean_d x + output conv =====================
    const float fact = factor[0];
    float mx0 = 0.f, mx1 = 0.f;
    #pragma unroll 4
    for (int t = 0; t < 32; ++t) {
        int dd = (lane + t) & 31;
        mx0 += xw[lane * 32 + dd];
        mx1 += xw[(lane + 32) * 32 + dd];
    }
    float ac0 = 0.f, ac1 = 0.f;
    #pragma unroll 4
    for (int s = 0; s < S; ++s) {
        float om = bufQ[s];
        ac0 += sm[OFF_WOT + s * CH + lane]      * om;
        ac1 += sm[OFF_WOT + s * CH + lane + 32] * om;
    }
    float r0 = mx0 * (1.0f / 32.0f) + fact * (ac0 + sm[OFF_BO + lane]);
    float r1 = mx1 * (1.0f / 32.0f) + fact * (ac1 + sm[OFF_BO + lane + 32]);
    sm[OFF_OUT + lane * 8 + warp]        = r0;
    sm[OFF_OUT + (lane + 32) * 8 + warp] = r1;

    __syncthreads();
    for (int e = tid; e < CH * WT; e += 256) {
        int c = e >> 3, wl = e & 7;
        out[(((size_t)b * CH + c) * H + h) * W + w0 + wl] = sm[OFF_OUT + e];
    }
}

extern "C" void kernel_launch(void* const* d_in, const int* in_sizes, int n_in,
                              void* d_out, int out_size)
{
    (void)in_sizes; (void)n_in; (void)out_size;
    const float* x      = (const float*)d_in[0];
    const float* Wk     = (const float*)d_in[1];
    const float* bk     = (const float*)d_in[2];
    const float* Wq     = (const float*)d_in[3];
    const float* bq     = (const float*)d_in[4];
    const float* Wv     = (const float*)d_in[5];
    const float* bv     = (const float*)d_in[6];
    const float* Wo     = (const float*)d_in[7];
    const float* bo     = (const float*)d_in[8];
    const float* factor = (const float*)d_in[9];
    float* out = (float*)d_out;

    cudaFuncSetAttribute(attn_fused_kernel,
                         cudaFuncAttributeMaxDynamicSharedMemorySize,
                         (int)SMEM_BYTES);
    dim3 grid(B * H * (W / WT));   // 4096
    dim3 block(256);
    attn_fused_kernel<<<grid, block, SMEM_BYTES>>>(
        x, Wk, bk, Wq, bq, Wv, bv, Wo, bo, factor, out);
}

// round 6
// speedup vs baseline: 1.1378x; 1.1378x over previous
#include <cuda_runtime.h>
#include <cstdint>

// ---------------------------------------------------------------------------
// Attention_layer, R5: D/E fold (mean-before-V), v kept in registers,
// kT/qT scratch aliased over dead X buffer -> 110 KB smem -> 2 CTAs/SM.
// ---------------------------------------------------------------------------

#define ULL unsigned long long

__device__ __forceinline__ ULL d2(float x) {
    ULL r; asm("mov.b64 %0,{%1,%1};" : "=l"(r) : "f"(x)); return r;
}
__device__ __forceinline__ void fma2(ULL& a, ULL b, ULL c) {
    asm("fma.rn.f32x2 %0,%1,%2,%0;" : "+l"(a) : "l"(b), "l"(c));
}
__device__ __forceinline__ float2 unpk(ULL a) {
    float lo, hi; asm("mov.b64 {%0,%1},%2;" : "=f"(lo), "=f"(hi) : "l"(a));
    return make_float2(lo, hi);
}
__device__ __forceinline__ float ex2(float x) {
    float r; asm("ex2.approx.f32 %0,%1;" : "=f"(r) : "f"(x)); return r;
}

// Problem constants
static constexpr int B  = 8;
static constexpr int CH = 64;
static constexpr int D  = 32;
static constexpr int H  = 64;
static constexpr int W  = 64;
static constexpr int S  = 32;
static constexpr int WT = 8;            // positions (warps) per CTA
static constexpr int HW = H * W;

// Per-warp union region: X (2048 floats) OR kT(36*32)+qT(36*32)=2304 floats.
// UW mod 32 == 4 keeps the staging/store bank spread of the old layouts.
static constexpr int RP  = 36;
static constexpr int UW  = 2308;
static constexpr int QT_OFS = RP * S;                // 1152 -> qT at +1156 (16B aligned, mod32==4... use 1156)
static constexpr int QT_BASE = 1156;

// smem layout (floats)
static constexpr int OFF_U    = 0;                   // 8 * 2308 = 18464
static constexpr int OFF_WKT  = OFF_U + WT * UW;     // 18464
static constexpr int OFF_WQT  = OFF_WKT + CH * S;    // +2048
static constexpr int OFF_WVT  = OFF_WQT + CH * S;
static constexpr int OFF_WOT  = OFF_WVT + CH * S;    // [s][c] 32*64
static constexpr int OFF_BK   = OFF_WOT + S * CH;
static constexpr int OFF_BQ   = OFF_BK + S;
static constexpr int OFF_BV   = OFF_BQ + S;
static constexpr int OFF_BO   = OFF_BV + S;          // 64
static constexpr int OFF_AB   = OFF_BO + CH;         // abar/om: 8 warps * 32
static constexpr int OFF_OUT  = OFF_AB + WT * S;     // 512
static constexpr int SMEM_FLOATS = OFF_OUT + CH * WT;
static constexpr size_t SMEM_BYTES = (size_t)SMEM_FLOATS * 4;   // ~110.3 KB

__global__ __launch_bounds__(256, 2)
void attn_fused_kernel(const float* __restrict__ x,
                       const float* __restrict__ Wk, const float* __restrict__ bk,
                       const float* __restrict__ Wq, const float* __restrict__ bq,
                       const float* __restrict__ Wv, const float* __restrict__ bv,
                       const float* __restrict__ Wo, const float* __restrict__ bo,
                       const float* __restrict__ factor,
                       float* __restrict__ out)
{
    extern __shared__ float sm[];
    const int tid  = threadIdx.x;
    const int blk  = blockIdx.x;
    const int b    = blk >> 9;
    const int rem  = blk & 511;
    const int h    = rem >> 3;
    const int w0   = (rem & 7) << 3;

    // ---- Stage x tile: [c][d][w0..w0+7] gmem -> smem [w][c*32+d] ----
    const float* base_in = x + (size_t)b * (CH * D) * HW + h * W + w0;
    #pragma unroll 4
    for (int it = 0; it < 32; ++it) {
        int idx = it * 256 + tid;
        int cd  = idx >> 2;
        int w2  = (idx & 3) << 1;
        float2 v = *(const float2*)(base_in + (size_t)cd * HW + w2);
        sm[OFF_U + w2 * UW + cd]       = v.x;
        sm[OFF_U + (w2 + 1) * UW + cd] = v.y;
    }

    // ---- Stage weights (transposed) ----
    for (int i = tid; i < CH * S; i += 256) {
        int c = i >> 5, s = i & 31;
        sm[OFF_WKT + i] = Wk[s * CH + c];
        sm[OFF_WQT + i] = Wq[s * CH + c];
        sm[OFF_WVT + i] = Wv[s * CH + c];
        int s2 = i >> 6, c2 = i & 63;
        sm[OFF_WOT + i] = Wo[c2 * S + s2];
    }
    if (tid < S) {
        sm[OFF_BK + tid] = bk[tid];
        sm[OFF_BQ + tid] = bq[tid];
        sm[OFF_BV + tid] = bv[tid];
    }
    if (tid < CH) sm[OFF_BO + tid] = bo[tid];
    __syncthreads();

    const int warp = tid >> 5;
    const int lane = tid & 31;
    const int sg   = lane >> 3;  // 0..3
    const int jg   = lane & 7;   // 0..7

    float* xw    = sm + OFF_U + warp * UW;          // X now; kT/qT later
    float* kT    = xw;                              // aliases X (X dead first)
    float* qT    = xw + QT_BASE;
    float* ABARw = sm + OFF_AB + warp * S;

    const float* xbase  = xw + jg * 4;
    const float* wkbase = sm + OFF_WKT + sg * 8;
    const float* wqbase = sm + OFF_WQT + sg * 8;
    const float* wvbase = sm + OFF_WVT + sg * 8;

    // ---- x mean over d (needed in phase F; X dies before then) ----
    float mx0 = 0.f, mx1 = 0.f;
    #pragma unroll 8
    for (int t = 0; t < 32; ++t) {
        int dd = (lane + t) & 31;                    // rotated: conflict-free
        mx0 += xw[lane * 32 + dd];
        mx1 += xw[(lane + 32) * 32 + dd];
    }

    // ================= Phase V: v projection (stays in registers) ==========
    ULL av[4][4];
    {
        const ULL* bv2 = (const ULL*)(sm + OFF_BV);
        #pragma unroll
        for (int sp = 0; sp < 4; ++sp) {
            ULL bV = bv2[sg * 4 + sp];
            #pragma unroll
            for (int td = 0; td < 4; ++td) av[sp][td] = bV;
        }
        #pragma unroll 4
        for (int c = 0; c < CH; ++c) {
            float4 xv = *(const float4*)(xbase + c * 32);
            ulonglong2 wva = ((const ulonglong2*)(wvbase + c * 32))[0];
            ulonglong2 wvb = ((const ulonglong2*)(wvbase + c * 32))[1];
            ULL xd[4] = {d2(xv.x), d2(xv.y), d2(xv.z), d2(xv.w)};
            #pragma unroll
            for (int td = 0; td < 4; ++td) {
                fma2(av[0][td], wva.x, xd[td]); fma2(av[1][td], wva.y, xd[td]);
                fma2(av[2][td], wvb.x, xd[td]); fma2(av[3][td], wvb.y, xd[td]);
            }
        }
    }

    // ================= Phase KQ: k and q projections =======================
    ULL ak[4][4], aq[4][4];
    {
        const ULL* bk2 = (const ULL*)(sm + OFF_BK);
        const ULL* bq2 = (const ULL*)(sm + OFF_BQ);
        #pragma unroll
        for (int sp = 0; sp < 4; ++sp) {
            ULL bK = bk2[sg * 4 + sp], bQ = bq2[sg * 4 + sp];
            #pragma unroll
            for (int td = 0; td < 4; ++td) { ak[sp][td] = bK; aq[sp][td] = bQ; }
        }
        #pragma unroll 4
        for (int c = 0; c < CH; ++c) {
            float4 xv = *(const float4*)(xbase + c * 32);
            ulonglong2 wka = ((const ulonglong2*)(wkbase + c * 32))[0];
            ulonglong2 wkb = ((const ulonglong2*)(wkbase + c * 32))[1];
            ulonglong2 wqa = ((const ulonglong2*)(wqbase + c * 32))[0];
            ulonglong2 wqb = ((const ulonglong2*)(wqbase + c * 32))[1];
            ULL xd[4] = {d2(xv.x), d2(xv.y), d2(xv.z), d2(xv.w)};
            #pragma unroll
            for (int td = 0; td < 4; ++td) {
                fma2(ak[0][td], wka.x, xd[td]); fma2(ak[1][td], wka.y, xd[td]);
                fma2(ak[2][td], wkb.x, xd[td]); fma2(ak[3][td], wkb.y, xd[td]);
                fma2(aq[0][td], wqa.x, xd[td]); fma2(aq[1][td], wqa.y, xd[td]);
                fma2(aq[2][td], wqb.x, xd[td]); fma2(aq[3][td], wqb.y, xd[td]);
            }
        }
    }
    __syncwarp();
    // X dead -> store kT/qT transposed [d][s] over the X region
    #pragma unroll
    for (int td = 0; td < 4; ++td) {
        int d = jg * 4 + td;
        ULL* kr = (ULL*)(kT + d * RP + sg * 8);
        ULL* qr = (ULL*)(qT + d * RP + sg * 8);
        #pragma unroll
        for (int sp = 0; sp < 4; ++sp) { kr[sp] = ak[sp][td]; qr[sp] = aq[sp][td]; }
    }
    __syncwarp();

    // ================= Phase B: scores[i][j] = sum_s k[s][i] q[s][j] =======
    ULL acc[8][4];
    #pragma unroll
    for (int ti = 0; ti < 8; ++ti)
        #pragma unroll
        for (int tj = 0; tj < 4; ++tj) acc[ti][tj] = 0ull;

    #pragma unroll 2
    for (int sq = 0; sq < 8; ++sq) {
        ulonglong2 kk[8];
        #pragma unroll
        for (int ti = 0; ti < 8; ++ti)
            kk[ti] = *(const ulonglong2*)(kT + (4 * ti + sg) * RP + sq * 4);
        ulonglong2 qq[4];
        #pragma unroll
        for (int tj = 0; tj < 4; ++tj)
            qq[tj] = *(const ulonglong2*)(qT + (8 * tj + jg) * RP + sq * 4);
        #pragma unroll
        for (int ti = 0; ti < 8; ++ti)
            #pragma unroll
            for (int tj = 0; tj < 4; ++tj) {
                fma2(acc[ti][tj], kk[ti].x, qq[tj].x);
                fma2(acc[ti][tj], kk[ti].y, qq[tj].y);
            }
    }
    float sc[8][4];
    #pragma unroll
    for (int ti = 0; ti < 8; ++ti)
        #pragma unroll
        for (int tj = 0; tj < 4; ++tj) { float2 u = unpk(acc[ti][tj]); sc[ti][tj] = u.x + u.y; }

    // ================= Phase C: softmax over i (per column j) ==============
    const float CEXP = 0.17677669529663687f * 1.44269504088896340f;
    #pragma unroll
    for (int tj = 0; tj < 4; ++tj) {
        float m = sc[0][tj];
        #pragma unroll
        for (int ti = 1; ti < 8; ++ti) m = fmaxf(m, sc[ti][tj]);
        m = fmaxf(m, __shfl_xor_sync(0xffffffffu, m, 8));
        m = fmaxf(m, __shfl_xor_sync(0xffffffffu, m, 16));
        float sum = 0.f;
        #pragma unroll
        for (int ti = 0; ti < 8; ++ti) {
            float e = ex2((sc[ti][tj] - m) * CEXP);
            sc[ti][tj] = e; sum += e;
        }
        sum += __shfl_xor_sync(0xffffffffu, sum, 8);
        sum += __shfl_xor_sync(0xffffffffu, sum, 16);
        float r = 1.0f / sum;
        #pragma unroll
        for (int ti = 0; ti < 8; ++ti) sc[ti][tj] *= r;
    }

    // ---- abar[i] = (1/32) * sum_j a[i][j]  (fold: mean over j before V) ---
    float ab[8];
    #pragma unroll
    for (int ti = 0; ti < 8; ++ti)
        ab[ti] = (sc[ti][0] + sc[ti][1]) + (sc[ti][2] + sc[ti][3]);
    #pragma unroll
    for (int ti = 0; ti < 8; ++ti) {
        ab[ti] += __shfl_xor_sync(0xffffffffu, ab[ti], 1);
        ab[ti] += __shfl_xor_sync(0xffffffffu, ab[ti], 2);
        ab[ti] += __shfl_xor_sync(0xffffffffu, ab[ti], 4);
    }
    if (jg == 0) {
        #pragma unroll
        for (int ti = 0; ti < 8; ++ti)
            ABARw[4 * ti + sg] = ab[ti] * (1.0f / 32.0f);
    }
    __syncwarp();

    // ================= Phase D': om[s] = sum_d v[s][d] * abar[d] ==========
    float4 ab4 = *(const float4*)(ABARw + jg * 4);   // d = 4*jg + td
    ULL ao[4] = {0ull, 0ull, 0ull, 0ull};
    {
        ULL a0 = d2(ab4.x), a1 = d2(ab4.y), a2 = d2(ab4.z), a3 = d2(ab4.w);
        #pragma unroll
        for (int sp = 0; sp < 4; ++sp) {
            fma2(ao[sp], av[sp][0], a0);
            fma2(ao[sp], av[sp][1], a1);
            fma2(ao[sp], av[sp][2], a2);
            fma2(ao[sp], av[sp][3], a3);
        }
    }
    __syncwarp();
    #pragma unroll
    for (int sp = 0; sp < 4; ++sp) {
        float2 u = unpk(ao[sp]);
        float o0 = u.x, o1 = u.y;
        o0 += __shfl_xor_sync(0xffffffffu, o0, 1);
        o0 += __shfl_xor_sync(0xffffffffu, o0, 2);
        o0 += __shfl_xor_sync(0xffffffffu, o0, 4);
        o1 += __shfl_xor_sync(0xffffffffu, o1, 1);
        o1 += __shfl_xor_sync(0xffffffffu, o1, 2);
        o1 += __shfl_xor_sync(0xffffffffu, o1, 4);
        if (jg == 0) {
            ABARw[sg * 8 + 2 * sp]     = o0;        // om overwrites abar
            ABARw[sg * 8 + 2 * sp + 1] = o1;
        }
    }
    __syncwarp();

    // ================= Phase F: out = mean_d(x) + f*(Wo*om + bo) ===========
    const float fact = factor[0];
    float ac0 = 0.f, ac1 = 0.f;
    #pragma unroll 8
    for (int s = 0; s < S; ++s) {
        float om = ABARw[s];
        ac0 += sm[OFF_WOT + s * CH + lane]      * om;
        ac1 += sm[OFF_WOT + s * CH + lane + 32] * om;
    }
    float r0 = mx0 * (1.0f / 32.0f) + fact * (ac0 + sm[OFF_BO + lane]);
    float r1 = mx1 * (1.0f / 32.0f) + fact * (ac1 + sm[OFF_BO + lane + 32]);
    sm[OFF_OUT + lane * 8 + warp]        = r0;
    sm[OFF_OUT + (lane + 32) * 8 + warp] = r1;

    __syncthreads();
    // coalesced output: out[b][c][h][w0..w0+7]
    for (int e = tid; e < CH * WT; e += 256) {
        int c = e >> 3, wl = e & 7;
        out[(((size_t)b * CH + c) * H + h) * W + w0 + wl] = sm[OFF_OUT + e];
    }
}

extern "C" void kernel_launch(void* const* d_in, const int* in_sizes, int n_in,
                              void* d_out, int out_size)
{
    (void)in_sizes; (void)n_in; (void)out_size;
    const float* x      = (const float*)d_in[0];
    const float* Wk     = (const float*)d_in[1];
    const float* bk     = (const float*)d_in[2];
    const float* Wq     = (const float*)d_in[3];
    const float* bq     = (const float*)d_in[4];
    const float* Wv     = (const float*)d_in[5];
    const float* bv     = (const float*)d_in[6];
    const float* Wo     = (const float*)d_in[7];
    const float* bo     = (const float*)d_in[8];
    const float* factor = (const float*)d_in[9];
    float* out = (float*)d_out;

    cudaFuncSetAttribute(attn_fused_kernel,
                         cudaFuncAttributeMaxDynamicSharedMemorySize,
                         (int)SMEM_BYTES);
    dim3 grid(B * H * (W / WT));   // 4096
    dim3 block(256);
    attn_fused_kernel<<<grid, block, SMEM_BYTES>>>(
        x, Wk, bk, Wq, bq, Wv, bv, Wo, bo, factor, out);
}